// round 5
// baseline (speedup 1.0000x reference)
#include <cuda_runtime.h>
#include <cstdint>

// Problem constants
#define Bb     8
#define Ll     4096
#define Dd     1024
#define Hh     16
#define BLK    4
#define HDIM   64
#define MTOT   (Bb*Ll)        // 32768
#define NQKV   (3*Dd)         // 3072

// Scratch (no cudaMalloc allowed)
__device__ float g_qkv[100663296];  // 32768 * 3072
__device__ float g_o[33554432];     // attention out (tf32-rounded)
__device__ float g_xt[33554432];    // x pre-rounded
__device__ float g_wqt[3145728];    // W_qkv pre-rounded
__device__ float g_wpt[1048576];    // W_proj pre-rounded

// ---------------------------------------------------------------------------
__device__ __forceinline__ uint32_t smem_u32(const void* p) {
    uint32_t a;
    asm("{ .reg .u64 t; cvta.to.shared.u64 t, %1; cvt.u32.u64 %0, t; }" : "=r"(a) : "l"(p));
    return a;
}

__device__ __forceinline__ float tf32r(float f) {
    uint32_t r;
    asm("cvt.rna.tf32.f32 %0, %1;" : "=r"(r) : "f"(f));
    return __uint_as_float(r);
}

__device__ __forceinline__ void cpasync16(uint32_t dst, const void* src) {
    asm volatile("cp.async.cg.shared.global [%0], [%1], 16;" :: "r"(dst), "l"(src));
}
#define CP_COMMIT() asm volatile("cp.async.commit_group;" ::: "memory")
#define CP_WAIT2()  asm volatile("cp.async.wait_group 2;" ::: "memory")

__device__ __forceinline__ void mma_tf32(float c[4], const uint32_t a[4], const uint32_t b[2]) {
    asm volatile(
        "mma.sync.aligned.m16n8k8.row.col.f32.tf32.tf32.f32 "
        "{%0,%1,%2,%3}, {%4,%5,%6,%7}, {%8,%9}, {%0,%1,%2,%3};\n"
        : "+f"(c[0]), "+f"(c[1]), "+f"(c[2]), "+f"(c[3])
        : "r"(a[0]), "r"(a[1]), "r"(a[2]), "r"(a[3]),
          "r"(b[0]), "r"(b[1]));
}

// ---------------------------------------------------------------------------
__global__ __launch_bounds__(256)
void tf32_round_kernel(const float4* __restrict__ in, float4* __restrict__ out, int n4)
{
    int i = blockIdx.x * blockDim.x + threadIdx.x;
    int stride = gridDim.x * blockDim.x;
    for (; i < n4; i += stride) {
        float4 v = in[i];
        v.x = tf32r(v.x); v.y = tf32r(v.y);
        v.z = tf32r(v.z); v.w = tf32r(v.w);
        out[i] = v;
    }
}

// ---------------------------------------------------------------------------
// TF32 GEMM via mma.sync. CTA 128x128, BK=64, 512 threads, 16 warps of 32x32.
// Inputs PRE-ROUNDED to tf32 bits. 3-stage cp.async pipeline.
// A smem: K-major 256B rows (two SW128 halves), ldmatrix.x4.
// B smem: K-major rows of 136 floats (stride 8 mod 32 -> conflict-free LDS).
// Fragments double-buffered across the 8 k-steps.
// Requires M%128==0, N%128==0, K%64==0.
// ---------------------------------------------------------------------------
#define A_STAGE 32768
#define B_ROWF  136
#define B_ROWB  544
#define B_STAGE 34816                        // 64 * 544
#define STAGES  3
#define GEMM_SMEM (STAGES * (A_STAGE + B_STAGE))   // 202752
#define BKC 64

__global__ __launch_bounds__(512, 1)
void gemm_mma_kernel(const float* __restrict__ A, const float* __restrict__ W,
                     const float* __restrict__ bias, float* __restrict__ C,
                     int N, int K)
{
    extern __shared__ char dsm[];
    const uint32_t sbase = smem_u32(dsm);

    const int tid  = threadIdx.x;
    const int wid  = tid >> 5;
    const int lane = tid & 31;
    const int warpM = wid & 3;       // 4 groups of 32 rows
    const int warpN = wid >> 2;      // 4 groups of 32 cols

    const int m0 = blockIdx.y * 128;
    const int n0 = blockIdx.x * 128;
    const int NC = K >> 6;           // chunks of 64

    // ---- staging pointers (precomputed, incremented per chunk) ----
    const float* aSrcP[4];
    const float* bSrcP[4];
    uint32_t aRel[4], bRel[4];
#pragma unroll
    for (int it = 0; it < 4; ++it) {
        int idx = tid + it * 512;
        int am = idx >> 4, ak = idx & 15;                 // A: 128 rows x 16 chunks
        aSrcP[it] = A + (size_t)(m0 + am) * K + ak * 4;
        aRel[it]  = am * 256 + ((ak & 8) << 4) + (((ak & 7) ^ (am & 7)) << 4);
        int bk = idx >> 5, bn = idx & 31;                 // B: 64 rows x 32 chunks
        bSrcP[it] = W + (size_t)bk * N + n0 + bn * 4;
        bRel[it]  = bk * B_ROWB + bn * 16;
    }

    auto stageF = [&](int s) {
        uint32_t aBase = sbase + s * A_STAGE;
        uint32_t bBase = sbase + STAGES * A_STAGE + s * B_STAGE;
#pragma unroll
        for (int it = 0; it < 4; ++it) {
            cpasync16(aBase + aRel[it], aSrcP[it]);
            aSrcP[it] += BKC;
        }
#pragma unroll
        for (int it = 0; it < 4; ++it) {
            cpasync16(bBase + bRel[it], bSrcP[it]);
            bSrcP[it] += (size_t)BKC * N;
        }
    };

    stageF(0); CP_COMMIT();
    stageF(1); CP_COMMIT();

    // ---- fragment address precompute ----
    const int r8  = lane & 7;
    const int sel = lane >> 3;
    const int rowAdd = r8 + ((sel & 2) << 2);
    const int colAdd = sel & 1;
    uint32_t colPart[8];
#pragma unroll
    for (int ks = 0; ks < 8; ++ks) {
        int c16 = 2 * ks + colAdd;
        colPart[ks] = ((c16 & 8) << 4) | (((c16 & 7) ^ r8) << 4);
    }
    uint32_t rowBase[2];
#pragma unroll
    for (int mt = 0; mt < 2; ++mt)
        rowBase[mt] = (uint32_t)(warpM * 32 + mt * 16 + rowAdd) * 256;
    const int laneB = (lane & 3) * B_ROWF + warpN * 32 + (lane >> 2);

    float acc[2][4][4];
#pragma unroll
    for (int mt = 0; mt < 2; ++mt)
#pragma unroll
        for (int nt = 0; nt < 4; ++nt)
#pragma unroll
            for (int r = 0; r < 4; ++r) acc[mt][nt][r] = 0.0f;

    uint32_t aF[2][2][4], bF[2][4][2];

    for (int c = 0; c < NC; ++c) {
        if (c + 2 < NC) stageF((c + 2) % STAGES);
        CP_COMMIT();
        CP_WAIT2();
        __syncthreads();

        const uint32_t aB = sbase + (c % STAGES) * A_STAGE;
        const float* bp = (const float*)(dsm + STAGES * A_STAGE + (c % STAGES) * B_STAGE) + laneB;

        auto loadFrags = [&](int ks, int buf) {
#pragma unroll
            for (int mt = 0; mt < 2; ++mt) {
                uint32_t addr = aB + rowBase[mt] + colPart[ks];
                uint32_t r0, r1, r2, r3;
                asm volatile("ldmatrix.sync.aligned.m8n8.x4.shared.b16 {%0,%1,%2,%3}, [%4];"
                             : "=r"(r0), "=r"(r1), "=r"(r2), "=r"(r3) : "r"(addr));
                aF[buf][mt][0] = r0; aF[buf][mt][1] = r2;
                aF[buf][mt][2] = r1; aF[buf][mt][3] = r3;
            }
            const float* bq = bp + ks * (8 * B_ROWF);
#pragma unroll
            for (int nt = 0; nt < 4; ++nt) {
                bF[buf][nt][0] = __float_as_uint(bq[nt * 8]);
                bF[buf][nt][1] = __float_as_uint(bq[4 * B_ROWF + nt * 8]);
            }
        };

        loadFrags(0, 0);
#pragma unroll
        for (int ks = 0; ks < 8; ++ks) {
            const int cur = ks & 1;
            if (ks < 7) loadFrags(ks + 1, cur ^ 1);
#pragma unroll
            for (int mt = 0; mt < 2; ++mt)
#pragma unroll
                for (int nt = 0; nt < 4; ++nt)
                    mma_tf32(acc[mt][nt], aF[cur][mt], bF[cur][nt]);
        }
        __syncthreads();
    }

    // ---- epilogue: bias + STG.64 ----
    const int col0 = n0 + warpN * 32 + 2 * (lane & 3);
    float2 bv[4];
#pragma unroll
    for (int nt = 0; nt < 4; ++nt)
        bv[nt] = *(const float2*)(bias + col0 + nt * 8);

    const int row0 = m0 + warpM * 32 + (lane >> 2);
#pragma unroll
    for (int mt = 0; mt < 2; ++mt) {
        int r = row0 + mt * 16;
#pragma unroll
        for (int nt = 0; nt < 4; ++nt) {
            int cn = col0 + nt * 8;
            float2 v0, v1;
            v0.x = acc[mt][nt][0] + bv[nt].x;
            v0.y = acc[mt][nt][1] + bv[nt].y;
            v1.x = acc[mt][nt][2] + bv[nt].x;
            v1.y = acc[mt][nt][3] + bv[nt].y;
            *(float2*)(C + (size_t)r * N + cn)       = v0;
            *(float2*)(C + (size_t)(r + 8) * N + cn) = v1;
        }
    }
}

// ---------------------------------------------------------------------------
// Block attention: one warp per (b, h, block). BS=4, d=64.
// Output rounded to tf32 bits (feeds proj GEMM).
// ---------------------------------------------------------------------------
__global__ __launch_bounds__(256)
void block_attn_kernel(const float* __restrict__ qkv, float* __restrict__ o)
{
    const int gwarp = (blockIdx.x * blockDim.x + threadIdx.x) >> 5;
    const int lane  = threadIdx.x & 31;

    const int nb = gwarp & 1023;
    const int bh = gwarp >> 10;
    const int h  = bh & 15;
    const int b  = bh >> 4;
    const int l0 = nb * BLK;

    const size_t rowBase = ((size_t)(b * Ll + l0)) * NQKV + h * 192;

    float2 q[4], k[4], v[4];
#pragma unroll
    for (int i = 0; i < 4; ++i) {
        const float* p = qkv + rowBase + (size_t)i * NQKV + 2 * lane;
        q[i] = *(const float2*)(p);
        k[i] = *(const float2*)(p + 64);
        v[i] = *(const float2*)(p + 128);
    }

    float s[4][4];
#pragma unroll
    for (int i = 0; i < 4; ++i)
#pragma unroll
        for (int j = 0; j < 4; ++j)
            s[i][j] = fmaf(q[i].y, k[j].y, q[i].x * k[j].x);

#pragma unroll
    for (int i = 0; i < 4; ++i)
#pragma unroll
        for (int j = 0; j < 4; ++j)
#pragma unroll
            for (int off = 16; off > 0; off >>= 1)
                s[i][j] += __shfl_xor_sync(0xffffffffu, s[i][j], off);

    const float scale = 0.125f;
    float2 outv[4];
#pragma unroll
    for (int i = 0; i < 4; ++i) {
        float t0 = s[i][0] * scale, t1 = s[i][1] * scale;
        float t2 = s[i][2] * scale, t3 = s[i][3] * scale;
        float m = fmaxf(fmaxf(t0, t1), fmaxf(t2, t3));
        float e0 = __expf(t0 - m), e1 = __expf(t1 - m);
        float e2 = __expf(t2 - m), e3 = __expf(t3 - m);
        float inv = 1.0f / (e0 + e1 + e2 + e3);
        float p0 = e0 * inv, p1 = e1 * inv, p2 = e2 * inv, p3 = e3 * inv;
        float ox = p0 * v[0].x; ox = fmaf(p1, v[1].x, ox);
        ox = fmaf(p2, v[2].x, ox); ox = fmaf(p3, v[3].x, ox);
        float oy = p0 * v[0].y; oy = fmaf(p1, v[1].y, oy);
        oy = fmaf(p2, v[2].y, oy); oy = fmaf(p3, v[3].y, oy);
        outv[i].x = tf32r(ox); outv[i].y = tf32r(oy);
    }

    const size_t obase = ((size_t)(b * Ll + l0)) * Dd + h * HDIM + 2 * lane;
#pragma unroll
    for (int i = 0; i < 4; ++i)
        *(float2*)(o + obase + (size_t)i * Dd) = outv[i];
}

// ---------------------------------------------------------------------------
extern "C" void kernel_launch(void* const* d_in, const int* in_sizes, int n_in,
                              void* d_out, int out_size)
{
    const float* x     = (const float*)d_in[0];
    const float* Wqkv  = (const float*)d_in[1];
    const float* bqkv  = (const float*)d_in[2];
    const float* Wproj = (const float*)d_in[3];
    const float* bproj = (const float*)d_in[4];
    float* out = (float*)d_out;

    float *qkv, *ob, *xt, *wqt, *wpt;
    cudaGetSymbolAddress((void**)&qkv, g_qkv);
    cudaGetSymbolAddress((void**)&ob,  g_o);
    cudaGetSymbolAddress((void**)&xt,  g_xt);
    cudaGetSymbolAddress((void**)&wqt, g_wqt);
    cudaGetSymbolAddress((void**)&wpt, g_wpt);

    cudaFuncSetAttribute(gemm_mma_kernel,
                         cudaFuncAttributeMaxDynamicSharedMemorySize, GEMM_SMEM);

    // 0) pre-round to tf32 bits
    tf32_round_kernel<<<8192, 256>>>((const float4*)x,     (float4*)xt,  MTOT * Dd / 4);
    tf32_round_kernel<<<3072, 256>>>((const float4*)Wqkv,  (float4*)wqt, Dd * NQKV / 4);
    tf32_round_kernel<<<1024, 256>>>((const float4*)Wproj, (float4*)wpt, Dd * Dd / 4);

    // 1) qkv = x @ W_qkv + b_qkv   (32768 x 3072 x 1024)
    {
        dim3 grid(NQKV / 128, MTOT / 128);
        gemm_mma_kernel<<<grid, 512, GEMM_SMEM>>>(xt, wqt, bqkv, qkv, NQKV, Dd);
    }

    // 2) block attention (tf32-rounded output)
    {
        int nwarps = Bb * Hh * (Ll / BLK);
        block_attn_kernel<<<nwarps / 8, 256>>>(qkv, ob);
    }

    // 3) out = o @ W_proj + b_proj  (32768 x 1024 x 1024)
    {
        dim3 grid(Dd / 128, MTOT / 128);
        gemm_mma_kernel<<<grid, 512, GEMM_SMEM>>>(ob, wpt, bproj, out, Dd, Dd);
    }
}

// round 6
// speedup vs baseline: 1.1892x; 1.1892x over previous
#include <cuda_runtime.h>
#include <cstdint>

// Problem constants
#define Bb     8
#define Ll     4096
#define Dd     1024
#define Hh     16
#define BLK    4
#define HDIM   64
#define MTOT   (Bb*Ll)        // 32768
#define NQKV   (3*Dd)         // 3072

// Scratch (no cudaMalloc allowed)
__device__ float g_qkv[100663296];  // 32768 * 3072
__device__ float g_o[33554432];     // attention out (tf32-rounded)
__device__ float g_xt[33554432];    // x pre-rounded
__device__ float g_wqt[3145728];    // W_qkv transposed [3072][1024], tf32-rounded
__device__ float g_wpt[1048576];    // W_proj transposed [1024][1024], tf32-rounded

// ---------------------------------------------------------------------------
__device__ __forceinline__ uint32_t smem_u32(const void* p) {
    uint32_t a;
    asm("{ .reg .u64 t; cvta.to.shared.u64 t, %1; cvt.u32.u64 %0, t; }" : "=r"(a) : "l"(p));
    return a;
}

__device__ __forceinline__ float tf32r(float f) {
    uint32_t r;
    asm("cvt.rna.tf32.f32 %0, %1;" : "=r"(r) : "f"(f));
    return __uint_as_float(r);
}

__device__ __forceinline__ void cpasync16(uint32_t dst, const void* src) {
    asm volatile("cp.async.cg.shared.global [%0], [%1], 16;" :: "r"(dst), "l"(src));
}
#define CP_COMMIT() asm volatile("cp.async.commit_group;" ::: "memory")
#define CP_WAIT2()  asm volatile("cp.async.wait_group 2;" ::: "memory")

__device__ __forceinline__ void mma_tf32(float c[4], const uint32_t a[4], const uint32_t b[2]) {
    asm volatile(
        "mma.sync.aligned.m16n8k8.row.col.f32.tf32.tf32.f32 "
        "{%0,%1,%2,%3}, {%4,%5,%6,%7}, {%8,%9}, {%0,%1,%2,%3};\n"
        : "+f"(c[0]), "+f"(c[1]), "+f"(c[2]), "+f"(c[3])
        : "r"(a[0]), "r"(a[1]), "r"(a[2]), "r"(a[3]),
          "r"(b[0]), "r"(b[1]));
}

// ---------------------------------------------------------------------------
// Prologue kernels
// ---------------------------------------------------------------------------
__global__ __launch_bounds__(256)
void tf32_round_kernel(const float4* __restrict__ in, float4* __restrict__ out, int n4)
{
    int i = blockIdx.x * blockDim.x + threadIdx.x;
    int stride = gridDim.x * blockDim.x;
    for (; i < n4; i += stride) {
        float4 v = in[i];
        v.x = tf32r(v.x); v.y = tf32r(v.y);
        v.z = tf32r(v.z); v.w = tf32r(v.w);
        out[i] = v;
    }
}

// out[N][K] = tf32_round(in[K][N]^T). 32x32 tiles, 32x8 threads.
__global__ __launch_bounds__(256)
void transpose_tf32_kernel(const float* __restrict__ in, float* __restrict__ out,
                           int K, int N)
{
    __shared__ float t[32][33];
    const int n0 = blockIdx.x * 32;
    const int k0 = blockIdx.y * 32;
    const int tx = threadIdx.x & 31;
    const int ty = threadIdx.x >> 5;   // 0..7
#pragma unroll
    for (int j = 0; j < 4; ++j)
        t[ty + j * 8][tx] = in[(size_t)(k0 + ty + j * 8) * N + n0 + tx];
    __syncthreads();
#pragma unroll
    for (int j = 0; j < 4; ++j)
        out[(size_t)(n0 + ty + j * 8) * K + k0 + tx] = tf32r(t[tx][ty + j * 8]);
}

// ---------------------------------------------------------------------------
// TF32 GEMM via mma.sync. CTA 128x128, BK=32, 512 threads, 16 warps of 32x32.
// A [M][K] row-major, Bt [N][K] row-major — SAME smem layout for both:
// 128 rows x 32 f32 (128B rows), SW128 swizzle, fragments via ldmatrix.x4.
// 4-stage cp.async pipeline, ONE __syncthreads per chunk.
// Requires M%128==0, N%128==0, K%32==0, K>=96.
// ---------------------------------------------------------------------------
#define TILE_B  16384
#define STAGE_B 32768                  // A tile + B tile
#define STAGES  4
#define GEMM_SMEM (STAGES * STAGE_B)   // 131072
#define BKC 32

__global__ __launch_bounds__(512, 1)
void gemm_mma_kernel(const float* __restrict__ A, const float* __restrict__ Bt,
                     const float* __restrict__ bias, float* __restrict__ C,
                     int N, int K)
{
    extern __shared__ char dsm[];
    const uint32_t sbase = smem_u32(dsm);

    const int tid  = threadIdx.x;
    const int wid  = tid >> 5;
    const int lane = tid & 31;
    const int warpM = wid & 3;       // 4 groups of 32 rows
    const int warpN = wid >> 2;      // 4 groups of 32 cols

    const int m0 = blockIdx.y * 128;
    const int n0 = blockIdx.x * 128;
    const int NC = K >> 5;

    // ---- staging: per thread 2 A-chunks + 2 B-chunks of 16B per stage ----
    const float* aSrcP[2];
    const float* bSrcP[2];
    uint32_t rel[2];
#pragma unroll
    for (int it = 0; it < 2; ++it) {
        int idx = tid + it * 512;            // 0..1023
        int r = idx >> 3, k16 = idx & 7;     // row 0..127, 16B-chunk 0..7
        rel[it] = r * 128 + (((k16 ^ (r & 7)) << 4));
        aSrcP[it] = A  + (size_t)(m0 + r) * K + k16 * 4;
        bSrcP[it] = Bt + (size_t)(n0 + r) * K + k16 * 4;
    }

    auto stageF = [&](int s) {
        uint32_t aBase = sbase + s * STAGE_B;
        uint32_t bBase = aBase + TILE_B;
#pragma unroll
        for (int it = 0; it < 2; ++it) {
            cpasync16(aBase + rel[it], aSrcP[it]);
            aSrcP[it] += BKC;
        }
#pragma unroll
        for (int it = 0; it < 2; ++it) {
            cpasync16(bBase + rel[it], bSrcP[it]);
            bSrcP[it] += BKC;
        }
    };

    stageF(0); CP_COMMIT();
    stageF(1); CP_COMMIT();
    stageF(2); CP_COMMIT();

    // ---- fragment address precompute ----
    // x4 at 16-row group: mats {0,1}=rows 0-7 col16 c/c+1, {2,3}=rows 8-15.
    const int r8  = lane & 7;
    const int sel = lane >> 3;                 // 0..3
    const int rowAdd = r8 + ((sel & 2) << 2);  // +8 rows for mats 2,3
    const int colAdd = sel & 1;                // +1 16B col for mats 1,3
    uint32_t colPart[4];
#pragma unroll
    for (int ks = 0; ks < 4; ++ks)
        colPart[ks] = (uint32_t)(((2 * ks + colAdd) ^ r8) << 4);

    uint32_t aRow[2], bRow[2];
#pragma unroll
    for (int g = 0; g < 2; ++g) {
        aRow[g] = (uint32_t)(warpM * 32 + g * 16 + rowAdd) * 128;
        bRow[g] = (uint32_t)(warpN * 32 + g * 16 + rowAdd) * 128 + TILE_B;
    }

    float acc[2][4][4];
#pragma unroll
    for (int mt = 0; mt < 2; ++mt)
#pragma unroll
        for (int nt = 0; nt < 4; ++nt)
#pragma unroll
            for (int r = 0; r < 4; ++r) acc[mt][nt][r] = 0.0f;

    uint32_t aF[2][2][4], bF[2][4][2];

    for (int c = 0; c < NC; ++c) {
        CP_WAIT2();
        __syncthreads();
        if (c + 3 < NC) stageF((c + 3) & 3);
        CP_COMMIT();

        const uint32_t sB = sbase + (c & 3) * STAGE_B;

        auto loadFrags = [&](int ks, int buf) {
            uint32_t cp = colPart[ks];
#pragma unroll
            for (int mt = 0; mt < 2; ++mt) {
                uint32_t r0, r1, r2, r3;
                asm volatile("ldmatrix.sync.aligned.m8n8.x4.shared.b16 {%0,%1,%2,%3}, [%4];"
                             : "=r"(r0), "=r"(r1), "=r"(r2), "=r"(r3)
                             : "r"(sB + aRow[mt] + cp));
                // A m16k8 frag: {a0,a1,a2,a3} = {r0, r2, r1, r3}
                aF[buf][mt][0] = r0; aF[buf][mt][1] = r2;
                aF[buf][mt][2] = r1; aF[buf][mt][3] = r3;
            }
#pragma unroll
            for (int g = 0; g < 2; ++g) {
                uint32_t r0, r1, r2, r3;
                asm volatile("ldmatrix.sync.aligned.m8n8.x4.shared.b16 {%0,%1,%2,%3}, [%4];"
                             : "=r"(r0), "=r"(r1), "=r"(r2), "=r"(r3)
                             : "r"(sB + bRow[g] + cp));
                // B n8k8 frags: rows 0-7 -> {r0,r1}; rows 8-15 -> {r2,r3}
                bF[buf][g * 2][0]     = r0; bF[buf][g * 2][1]     = r1;
                bF[buf][g * 2 + 1][0] = r2; bF[buf][g * 2 + 1][1] = r3;
            }
        };

        loadFrags(0, 0);
#pragma unroll
        for (int ks = 0; ks < 4; ++ks) {
            const int cur = ks & 1;
            if (ks < 3) loadFrags(ks + 1, cur ^ 1);
#pragma unroll
            for (int mt = 0; mt < 2; ++mt)
#pragma unroll
                for (int nt = 0; nt < 4; ++nt)
                    mma_tf32(acc[mt][nt], aF[cur][mt], bF[cur][nt]);
        }
    }

    // ---- epilogue: bias + STG.64 ----
    const int col0 = n0 + warpN * 32 + 2 * (lane & 3);
    float2 bv[4];
#pragma unroll
    for (int nt = 0; nt < 4; ++nt)
        bv[nt] = *(const float2*)(bias + col0 + nt * 8);

    const int row0 = m0 + warpM * 32 + (lane >> 2);
#pragma unroll
    for (int mt = 0; mt < 2; ++mt) {
        int r = row0 + mt * 16;
#pragma unroll
        for (int nt = 0; nt < 4; ++nt) {
            int cn = col0 + nt * 8;
            float2 v0, v1;
            v0.x = acc[mt][nt][0] + bv[nt].x;
            v0.y = acc[mt][nt][1] + bv[nt].y;
            v1.x = acc[mt][nt][2] + bv[nt].x;
            v1.y = acc[mt][nt][3] + bv[nt].y;
            *(float2*)(C + (size_t)r * N + cn)       = v0;
            *(float2*)(C + (size_t)(r + 8) * N + cn) = v1;
        }
    }
}

// ---------------------------------------------------------------------------
// Block attention: one warp per (b, h, block). BS=4, d=64.
// Output rounded to tf32 bits (feeds proj GEMM).
// ---------------------------------------------------------------------------
__global__ __launch_bounds__(256)
void block_attn_kernel(const float* __restrict__ qkv, float* __restrict__ o)
{
    const int gwarp = (blockIdx.x * blockDim.x + threadIdx.x) >> 5;
    const int lane  = threadIdx.x & 31;

    const int nb = gwarp & 1023;
    const int bh = gwarp >> 10;
    const int h  = bh & 15;
    const int b  = bh >> 4;
    const int l0 = nb * BLK;

    const size_t rowBase = ((size_t)(b * Ll + l0)) * NQKV + h * 192;

    float2 q[4], k[4], v[4];
#pragma unroll
    for (int i = 0; i < 4; ++i) {
        const float* p = qkv + rowBase + (size_t)i * NQKV + 2 * lane;
        q[i] = *(const float2*)(p);
        k[i] = *(const float2*)(p + 64);
        v[i] = *(const float2*)(p + 128);
    }

    float s[4][4];
#pragma unroll
    for (int i = 0; i < 4; ++i)
#pragma unroll
        for (int j = 0; j < 4; ++j)
            s[i][j] = fmaf(q[i].y, k[j].y, q[i].x * k[j].x);

#pragma unroll
    for (int i = 0; i < 4; ++i)
#pragma unroll
        for (int j = 0; j < 4; ++j)
#pragma unroll
            for (int off = 16; off > 0; off >>= 1)
                s[i][j] += __shfl_xor_sync(0xffffffffu, s[i][j], off);

    const float scale = 0.125f;
    float2 outv[4];
#pragma unroll
    for (int i = 0; i < 4; ++i) {
        float t0 = s[i][0] * scale, t1 = s[i][1] * scale;
        float t2 = s[i][2] * scale, t3 = s[i][3] * scale;
        float m = fmaxf(fmaxf(t0, t1), fmaxf(t2, t3));
        float e0 = __expf(t0 - m), e1 = __expf(t1 - m);
        float e2 = __expf(t2 - m), e3 = __expf(t3 - m);
        float inv = 1.0f / (e0 + e1 + e2 + e3);
        float p0 = e0 * inv, p1 = e1 * inv, p2 = e2 * inv, p3 = e3 * inv;
        float ox = p0 * v[0].x; ox = fmaf(p1, v[1].x, ox);
        ox = fmaf(p2, v[2].x, ox); ox = fmaf(p3, v[3].x, ox);
        float oy = p0 * v[0].y; oy = fmaf(p1, v[1].y, oy);
        oy = fmaf(p2, v[2].y, oy); oy = fmaf(p3, v[3].y, oy);
        outv[i].x = tf32r(ox); outv[i].y = tf32r(oy);
    }

    const size_t obase = ((size_t)(b * Ll + l0)) * Dd + h * HDIM + 2 * lane;
#pragma unroll
    for (int i = 0; i < 4; ++i)
        *(float2*)(o + obase + (size_t)i * Dd) = outv[i];
}

// ---------------------------------------------------------------------------
extern "C" void kernel_launch(void* const* d_in, const int* in_sizes, int n_in,
                              void* d_out, int out_size)
{
    const float* x     = (const float*)d_in[0];
    const float* Wqkv  = (const float*)d_in[1];
    const float* bqkv  = (const float*)d_in[2];
    const float* Wproj = (const float*)d_in[3];
    const float* bproj = (const float*)d_in[4];
    float* out = (float*)d_out;

    float *qkv, *ob, *xt, *wqt, *wpt;
    cudaGetSymbolAddress((void**)&qkv, g_qkv);
    cudaGetSymbolAddress((void**)&ob,  g_o);
    cudaGetSymbolAddress((void**)&xt,  g_xt);
    cudaGetSymbolAddress((void**)&wqt, g_wqt);
    cudaGetSymbolAddress((void**)&wpt, g_wpt);

    cudaFuncSetAttribute(gemm_mma_kernel,
                         cudaFuncAttributeMaxDynamicSharedMemorySize, GEMM_SMEM);

    // 0) pre-round x; transpose+round weights (Wt[N][K])
    tf32_round_kernel<<<8192, 256>>>((const float4*)x, (float4*)xt, MTOT * Dd / 4);
    {
        dim3 g1(NQKV / 32, Dd / 32);
        transpose_tf32_kernel<<<g1, 256>>>(Wqkv, wqt, Dd, NQKV);
        dim3 g2(Dd / 32, Dd / 32);
        transpose_tf32_kernel<<<g2, 256>>>(Wproj, wpt, Dd, Dd);
    }

    // 1) qkv = x @ W_qkv + b_qkv   (32768 x 3072 x 1024)
    {
        dim3 grid(NQKV / 128, MTOT / 128);
        gemm_mma_kernel<<<grid, 512, GEMM_SMEM>>>(xt, wqt, bqkv, qkv, NQKV, Dd);
    }

    // 2) block attention (tf32-rounded output)
    {
        int nwarps = Bb * Hh * (Ll / BLK);
        block_attn_kernel<<<nwarps / 8, 256>>>(qkv, ob);
    }

    // 3) out = o @ W_proj + b_proj  (32768 x 1024 x 1024)
    {
        dim3 grid(Dd / 128, MTOT / 128);
        gemm_mma_kernel<<<grid, 512, GEMM_SMEM>>>(ob, wpt, bproj, out, Dd, Dd);
    }
}

// round 7
// speedup vs baseline: 1.2119x; 1.0191x over previous
#include <cuda_runtime.h>
#include <cstdint>

// Problem constants
#define Bb     8
#define Ll     4096
#define Dd     1024
#define Hh     16
#define BLK    4
#define HDIM   64
#define MTOT   (Bb*Ll)        // 32768
#define NQKV   (3*Dd)         // 3072

// Scratch (no cudaMalloc allowed)
__device__ float g_qkv[100663296];  // 32768 * 3072
__device__ float g_o[33554432];     // attention out (tf32-rounded)
__device__ float g_xt[33554432];    // x pre-rounded
__device__ float g_wqt[3145728];    // W_qkv transposed [3072][1024], tf32-rounded
__device__ float g_wpt[1048576];    // W_proj transposed [1024][1024], tf32-rounded

// ---------------------------------------------------------------------------
__device__ __forceinline__ uint32_t smem_u32(const void* p) {
    uint32_t a;
    asm("{ .reg .u64 t; cvta.to.shared.u64 t, %1; cvt.u32.u64 %0, t; }" : "=r"(a) : "l"(p));
    return a;
}

__device__ __forceinline__ float tf32r(float f) {
    uint32_t r;
    asm("cvt.rna.tf32.f32 %0, %1;" : "=r"(r) : "f"(f));
    return __uint_as_float(r);
}

__device__ __forceinline__ void cpasync16(uint32_t dst, const void* src) {
    asm volatile("cp.async.cg.shared.global [%0], [%1], 16;" :: "r"(dst), "l"(src));
}
#define CP_COMMIT() asm volatile("cp.async.commit_group;" ::: "memory")
#define CP_WAIT2()  asm volatile("cp.async.wait_group 2;" ::: "memory")

__device__ __forceinline__ void mma_tf32(float c[4], const uint32_t a[4], const uint32_t b[2]) {
    asm volatile(
        "mma.sync.aligned.m16n8k8.row.col.f32.tf32.tf32.f32 "
        "{%0,%1,%2,%3}, {%4,%5,%6,%7}, {%8,%9}, {%0,%1,%2,%3};\n"
        : "+f"(c[0]), "+f"(c[1]), "+f"(c[2]), "+f"(c[3])
        : "r"(a[0]), "r"(a[1]), "r"(a[2]), "r"(a[3]),
          "r"(b[0]), "r"(b[1]));
}

// ---------------------------------------------------------------------------
// Prologue kernels
// ---------------------------------------------------------------------------
__global__ __launch_bounds__(256)
void tf32_round_kernel(const float4* __restrict__ in, float4* __restrict__ out, int n4)
{
    int i = blockIdx.x * blockDim.x + threadIdx.x;
    int stride = gridDim.x * blockDim.x;
    for (; i < n4; i += stride) {
        float4 v = in[i];
        v.x = tf32r(v.x); v.y = tf32r(v.y);
        v.z = tf32r(v.z); v.w = tf32r(v.w);
        out[i] = v;
    }
}

// out[N][K] = tf32_round(in[K][N]^T). 32x32 tiles, 32x8 threads.
__global__ __launch_bounds__(256)
void transpose_tf32_kernel(const float* __restrict__ in, float* __restrict__ out,
                           int K, int N)
{
    __shared__ float t[32][33];
    const int n0 = blockIdx.x * 32;
    const int k0 = blockIdx.y * 32;
    const int tx = threadIdx.x & 31;
    const int ty = threadIdx.x >> 5;   // 0..7
#pragma unroll
    for (int j = 0; j < 4; ++j)
        t[ty + j * 8][tx] = in[(size_t)(k0 + ty + j * 8) * N + n0 + tx];
    __syncthreads();
#pragma unroll
    for (int j = 0; j < 4; ++j)
        out[(size_t)(n0 + ty + j * 8) * K + k0 + tx] = tf32r(t[tx][ty + j * 8]);
}

// ---------------------------------------------------------------------------
// TF32 GEMM via mma.sync. CTA 128(M) x 64(N), BK=32, 256 threads, 8 warps of
// 32x32, 2 CTAs/SM co-resident (latency hiding across barrier convoys).
// A [M][K] row-major, Bt [N][K] row-major — SAME smem layout:
// rows of 128B, SW128 swizzle, all fragments via ldmatrix.x4.
// 4-stage cp.async pipeline, ONE __syncthreads per chunk.
// Requires M%128==0, N%64==0, K%32==0, K>=96.
// ---------------------------------------------------------------------------
#define A_TILE  16384
#define B_TILE  8192
#define STAGE_B (A_TILE + B_TILE)      // 24576
#define STAGES  4
#define GEMM_SMEM (STAGES * STAGE_B)   // 98304
#define BKC 32

__global__ __launch_bounds__(256, 2)
void gemm_mma_kernel(const float* __restrict__ A, const float* __restrict__ Bt,
                     const float* __restrict__ bias, float* __restrict__ C,
                     int N, int K)
{
    extern __shared__ char dsm[];
    const uint32_t sbase = smem_u32(dsm);

    const int tid  = threadIdx.x;
    const int wid  = tid >> 5;
    const int lane = tid & 31;
    const int warpM = wid & 3;       // 4 groups of 32 rows
    const int warpN = wid >> 2;      // 2 groups of 32 cols

    const int m0 = blockIdx.y * 128;
    const int n0 = blockIdx.x * 64;
    const int NC = K >> 5;

    // ---- staging: per thread 4 A-chunks + 2 B-chunks of 16B per stage ----
    const float* aSrcP[4];
    const float* bSrcP[2];
    uint32_t aRel[4], bRel[2];
#pragma unroll
    for (int it = 0; it < 4; ++it) {
        int idx = tid + it * 256;            // 0..1023
        int r = idx >> 3, k16 = idx & 7;
        aRel[it] = r * 128 + (((k16 ^ (r & 7)) << 4));
        aSrcP[it] = A + (size_t)(m0 + r) * K + k16 * 4;
    }
#pragma unroll
    for (int it = 0; it < 2; ++it) {
        int idx = tid + it * 256;            // 0..511
        int r = idx >> 3, k16 = idx & 7;
        bRel[it] = r * 128 + (((k16 ^ (r & 7)) << 4));
        bSrcP[it] = Bt + (size_t)(n0 + r) * K + k16 * 4;
    }

    auto stageF = [&](int s) {
        uint32_t aBase = sbase + s * STAGE_B;
        uint32_t bBase = aBase + A_TILE;
#pragma unroll
        for (int it = 0; it < 4; ++it) {
            cpasync16(aBase + aRel[it], aSrcP[it]);
            aSrcP[it] += BKC;
        }
#pragma unroll
        for (int it = 0; it < 2; ++it) {
            cpasync16(bBase + bRel[it], bSrcP[it]);
            bSrcP[it] += BKC;
        }
    };

    stageF(0); CP_COMMIT();
    stageF(1); CP_COMMIT();
    stageF(2); CP_COMMIT();

    // ---- fragment address precompute ----
    const int r8  = lane & 7;
    const int sel = lane >> 3;                 // 0..3
    const int rowAdd = r8 + ((sel & 2) << 2);  // +8 rows for mats 2,3
    const int colAdd = sel & 1;                // +1 16B col for mats 1,3
    uint32_t colPart[4];
#pragma unroll
    for (int ks = 0; ks < 4; ++ks)
        colPart[ks] = (uint32_t)(((2 * ks + colAdd) ^ r8) << 4);

    uint32_t aRow[2], bRow[2];
#pragma unroll
    for (int g = 0; g < 2; ++g) {
        aRow[g] = (uint32_t)(warpM * 32 + g * 16 + rowAdd) * 128;
        bRow[g] = (uint32_t)(warpN * 32 + g * 16 + rowAdd) * 128 + A_TILE;
    }

    float acc[2][4][4];
#pragma unroll
    for (int mt = 0; mt < 2; ++mt)
#pragma unroll
        for (int nt = 0; nt < 4; ++nt)
#pragma unroll
            for (int r = 0; r < 4; ++r) acc[mt][nt][r] = 0.0f;

    uint32_t aF[2][2][4], bF[2][4][2];

    for (int c = 0; c < NC; ++c) {
        CP_WAIT2();
        __syncthreads();
        if (c + 3 < NC) stageF((c + 3) & 3);
        CP_COMMIT();

        const uint32_t sB = sbase + (c & 3) * STAGE_B;

        auto loadFrags = [&](int ks, int buf) {
            uint32_t cp = colPart[ks];
#pragma unroll
            for (int mt = 0; mt < 2; ++mt) {
                uint32_t r0, r1, r2, r3;
                asm volatile("ldmatrix.sync.aligned.m8n8.x4.shared.b16 {%0,%1,%2,%3}, [%4];"
                             : "=r"(r0), "=r"(r1), "=r"(r2), "=r"(r3)
                             : "r"(sB + aRow[mt] + cp));
                aF[buf][mt][0] = r0; aF[buf][mt][1] = r2;
                aF[buf][mt][2] = r1; aF[buf][mt][3] = r3;
            }
#pragma unroll
            for (int g = 0; g < 2; ++g) {
                uint32_t r0, r1, r2, r3;
                asm volatile("ldmatrix.sync.aligned.m8n8.x4.shared.b16 {%0,%1,%2,%3}, [%4];"
                             : "=r"(r0), "=r"(r1), "=r"(r2), "=r"(r3)
                             : "r"(sB + bRow[g] + cp));
                bF[buf][g * 2][0]     = r0; bF[buf][g * 2][1]     = r1;
                bF[buf][g * 2 + 1][0] = r2; bF[buf][g * 2 + 1][1] = r3;
            }
        };

        loadFrags(0, 0);
#pragma unroll
        for (int ks = 0; ks < 4; ++ks) {
            const int cur = ks & 1;
            if (ks < 3) loadFrags(ks + 1, cur ^ 1);
#pragma unroll
            for (int mt = 0; mt < 2; ++mt)
#pragma unroll
                for (int nt = 0; nt < 4; ++nt)
                    mma_tf32(acc[mt][nt], aF[cur][mt], bF[cur][nt]);
        }
    }

    // ---- epilogue: bias + STG.64 ----
    const int col0 = n0 + warpN * 32 + 2 * (lane & 3);
    float2 bv[4];
#pragma unroll
    for (int nt = 0; nt < 4; ++nt)
        bv[nt] = *(const float2*)(bias + col0 + nt * 8);

    const int row0 = m0 + warpM * 32 + (lane >> 2);
#pragma unroll
    for (int mt = 0; mt < 2; ++mt) {
        int r = row0 + mt * 16;
#pragma unroll
        for (int nt = 0; nt < 4; ++nt) {
            int cn = col0 + nt * 8;
            float2 v0, v1;
            v0.x = acc[mt][nt][0] + bv[nt].x;
            v0.y = acc[mt][nt][1] + bv[nt].y;
            v1.x = acc[mt][nt][2] + bv[nt].x;
            v1.y = acc[mt][nt][3] + bv[nt].y;
            *(float2*)(C + (size_t)r * N + cn)       = v0;
            *(float2*)(C + (size_t)(r + 8) * N + cn) = v1;
        }
    }
}

// ---------------------------------------------------------------------------
// Block attention: one warp per (b, h, block). BS=4, d=64.
// Output rounded to tf32 bits (feeds proj GEMM).
// ---------------------------------------------------------------------------
__global__ __launch_bounds__(256)
void block_attn_kernel(const float* __restrict__ qkv, float* __restrict__ o)
{
    const int gwarp = (blockIdx.x * blockDim.x + threadIdx.x) >> 5;
    const int lane  = threadIdx.x & 31;

    const int nb = gwarp & 1023;
    const int bh = gwarp >> 10;
    const int h  = bh & 15;
    const int b  = bh >> 4;
    const int l0 = nb * BLK;

    const size_t rowBase = ((size_t)(b * Ll + l0)) * NQKV + h * 192;

    float2 q[4], k[4], v[4];
#pragma unroll
    for (int i = 0; i < 4; ++i) {
        const float* p = qkv + rowBase + (size_t)i * NQKV + 2 * lane;
        q[i] = *(const float2*)(p);
        k[i] = *(const float2*)(p + 64);
        v[i] = *(const float2*)(p + 128);
    }

    float s[4][4];
#pragma unroll
    for (int i = 0; i < 4; ++i)
#pragma unroll
        for (int j = 0; j < 4; ++j)
            s[i][j] = fmaf(q[i].y, k[j].y, q[i].x * k[j].x);

#pragma unroll
    for (int i = 0; i < 4; ++i)
#pragma unroll
        for (int j = 0; j < 4; ++j)
#pragma unroll
            for (int off = 16; off > 0; off >>= 1)
                s[i][j] += __shfl_xor_sync(0xffffffffu, s[i][j], off);

    const float scale = 0.125f;
    float2 outv[4];
#pragma unroll
    for (int i = 0; i < 4; ++i) {
        float t0 = s[i][0] * scale, t1 = s[i][1] * scale;
        float t2 = s[i][2] * scale, t3 = s[i][3] * scale;
        float m = fmaxf(fmaxf(t0, t1), fmaxf(t2, t3));
        float e0 = __expf(t0 - m), e1 = __expf(t1 - m);
        float e2 = __expf(t2 - m), e3 = __expf(t3 - m);
        float inv = 1.0f / (e0 + e1 + e2 + e3);
        float p0 = e0 * inv, p1 = e1 * inv, p2 = e2 * inv, p3 = e3 * inv;
        float ox = p0 * v[0].x; ox = fmaf(p1, v[1].x, ox);
        ox = fmaf(p2, v[2].x, ox); ox = fmaf(p3, v[3].x, ox);
        float oy = p0 * v[0].y; oy = fmaf(p1, v[1].y, oy);
        oy = fmaf(p2, v[2].y, oy); oy = fmaf(p3, v[3].y, oy);
        outv[i].x = tf32r(ox); outv[i].y = tf32r(oy);
    }

    const size_t obase = ((size_t)(b * Ll + l0)) * Dd + h * HDIM + 2 * lane;
#pragma unroll
    for (int i = 0; i < 4; ++i)
        *(float2*)(o + obase + (size_t)i * Dd) = outv[i];
}

// ---------------------------------------------------------------------------
extern "C" void kernel_launch(void* const* d_in, const int* in_sizes, int n_in,
                              void* d_out, int out_size)
{
    const float* x     = (const float*)d_in[0];
    const float* Wqkv  = (const float*)d_in[1];
    const float* bqkv  = (const float*)d_in[2];
    const float* Wproj = (const float*)d_in[3];
    const float* bproj = (const float*)d_in[4];
    float* out = (float*)d_out;

    float *qkv, *ob, *xt, *wqt, *wpt;
    cudaGetSymbolAddress((void**)&qkv, g_qkv);
    cudaGetSymbolAddress((void**)&ob,  g_o);
    cudaGetSymbolAddress((void**)&xt,  g_xt);
    cudaGetSymbolAddress((void**)&wqt, g_wqt);
    cudaGetSymbolAddress((void**)&wpt, g_wpt);

    cudaFuncSetAttribute(gemm_mma_kernel,
                         cudaFuncAttributeMaxDynamicSharedMemorySize, GEMM_SMEM);

    // 0) pre-round x; transpose+round weights (Wt[N][K])
    tf32_round_kernel<<<8192, 256>>>((const float4*)x, (float4*)xt, MTOT * Dd / 4);
    {
        dim3 g1(NQKV / 32, Dd / 32);
        transpose_tf32_kernel<<<g1, 256>>>(Wqkv, wqt, Dd, NQKV);
        dim3 g2(Dd / 32, Dd / 32);
        transpose_tf32_kernel<<<g2, 256>>>(Wproj, wpt, Dd, Dd);
    }

    // 1) qkv = x @ W_qkv + b_qkv   (32768 x 3072 x 1024)
    {
        dim3 grid(NQKV / 64, MTOT / 128);
        gemm_mma_kernel<<<grid, 256, GEMM_SMEM>>>(xt, wqt, bqkv, qkv, NQKV, Dd);
    }

    // 2) block attention (tf32-rounded output)
    {
        int nwarps = Bb * Hh * (Ll / BLK);
        block_attn_kernel<<<nwarps / 8, 256>>>(qkv, ob);
    }

    // 3) out = o @ W_proj + b_proj  (32768 x 1024 x 1024)
    {
        dim3 grid(Dd / 64, MTOT / 128);
        gemm_mma_kernel<<<grid, 256, GEMM_SMEM>>>(ob, wpt, bproj, out, Dd, Dd);
    }
}

// round 8
// speedup vs baseline: 1.3369x; 1.1031x over previous
#include <cuda_runtime.h>
#include <cstdint>

// Problem constants
#define Bb     8
#define Ll     4096
#define Dd     1024
#define Hh     16
#define BLK    4
#define HDIM   64
#define MTOT   (Bb*Ll)        // 32768
#define NQKV   (3*Dd)         // 3072

// Scratch (no cudaMalloc allowed)
__device__ float g_qkv[100663296];  // 32768 * 3072
__device__ float g_o[33554432];     // attention out (tf32-rounded)
__device__ float g_xt[33554432];    // x pre-rounded
__device__ float g_wqt[3145728];    // W_qkv transposed [3072][1024], tf32-rounded
__device__ float g_wpt[1048576];    // W_proj transposed [1024][1024], tf32-rounded

// ---------------------------------------------------------------------------
__device__ __forceinline__ uint32_t smem_u32(const void* p) {
    uint32_t a;
    asm("{ .reg .u64 t; cvta.to.shared.u64 t, %1; cvt.u32.u64 %0, t; }" : "=r"(a) : "l"(p));
    return a;
}

__device__ __forceinline__ float tf32r(float f) {
    uint32_t r;
    asm("cvt.rna.tf32.f32 %0, %1;" : "=r"(r) : "f"(f));
    return __uint_as_float(r);
}

__device__ __forceinline__ void cpasync16(uint32_t dst, const void* src) {
    asm volatile("cp.async.cg.shared.global [%0], [%1], 16;" :: "r"(dst), "l"(src));
}
#define CP_COMMIT() asm volatile("cp.async.commit_group;" ::: "memory")
#define CP_WAIT1()  asm volatile("cp.async.wait_group 1;" ::: "memory")

__device__ __forceinline__ void mma_tf32(float c[4], const uint32_t a[4], const uint32_t b[2]) {
    asm volatile(
        "mma.sync.aligned.m16n8k8.row.col.f32.tf32.tf32.f32 "
        "{%0,%1,%2,%3}, {%4,%5,%6,%7}, {%8,%9}, {%0,%1,%2,%3};\n"
        : "+f"(c[0]), "+f"(c[1]), "+f"(c[2]), "+f"(c[3])
        : "r"(a[0]), "r"(a[1]), "r"(a[2]), "r"(a[3]),
          "r"(b[0]), "r"(b[1]));
}

// ---------------------------------------------------------------------------
// Prologue kernels
// ---------------------------------------------------------------------------
__global__ __launch_bounds__(256)
void tf32_round_kernel(const float4* __restrict__ in, float4* __restrict__ out, int n4)
{
    int i = blockIdx.x * blockDim.x + threadIdx.x;
    int stride = gridDim.x * blockDim.x;
    for (; i < n4; i += stride) {
        float4 v = in[i];
        v.x = tf32r(v.x); v.y = tf32r(v.y);
        v.z = tf32r(v.z); v.w = tf32r(v.w);
        out[i] = v;
    }
}

// out[N][K] = tf32_round(in[K][N]^T). 32x32 tiles, 32x8 threads.
__global__ __launch_bounds__(256)
void transpose_tf32_kernel(const float* __restrict__ in, float* __restrict__ out,
                           int K, int N)
{
    __shared__ float t[32][33];
    const int n0 = blockIdx.x * 32;
    const int k0 = blockIdx.y * 32;
    const int tx = threadIdx.x & 31;
    const int ty = threadIdx.x >> 5;   // 0..7
#pragma unroll
    for (int j = 0; j < 4; ++j)
        t[ty + j * 8][tx] = in[(size_t)(k0 + ty + j * 8) * N + n0 + tx];
    __syncthreads();
#pragma unroll
    for (int j = 0; j < 4; ++j)
        out[(size_t)(n0 + ty + j * 8) * K + k0 + tx] = tf32r(t[tx][ty + j * 8]);
}

// ---------------------------------------------------------------------------
// TF32 GEMM via mma.sync. CTA 128(M) x 64(N), BK=32, 256 threads, 8 warps of
// 32x32, 3 CTAs/SM (24 warps) for latency hiding. 3-stage cp.async pipeline,
// single-buffered fragments (occupancy over ILP).
// A [M][K] row-major, Bt [N][K] row-major — same smem layout (128B rows,
// SW128 swizzle), all fragments via ldmatrix.x4.
// Requires M%128==0, N%64==0, K%32==0, K>=64.
// ---------------------------------------------------------------------------
#define A_TILE  16384
#define B_TILE  8192
#define STAGE_B (A_TILE + B_TILE)      // 24576
#define STAGES  3
#define GEMM_SMEM (STAGES * STAGE_B)   // 73728
#define BKC 32

__global__ __launch_bounds__(256, 3)
void gemm_mma_kernel(const float* __restrict__ A, const float* __restrict__ Bt,
                     const float* __restrict__ bias, float* __restrict__ C,
                     int N, int K)
{
    extern __shared__ char dsm[];
    const uint32_t sbase = smem_u32(dsm);

    const int tid  = threadIdx.x;
    const int wid  = tid >> 5;
    const int lane = tid & 31;
    const int warpM = wid & 3;       // 4 groups of 32 rows
    const int warpN = wid >> 2;      // 2 groups of 32 cols

    const int m0 = blockIdx.y * 128;
    const int n0 = blockIdx.x * 64;
    const int NC = K >> 5;

    // ---- staging: one 64-bit base each + 32-bit byte offsets ----
    const char* Ab = (const char*)A;
    const char* Bb_ = (const char*)Bt;
    uint32_t aRel[4], bRel[2];   // smem offsets (constant)
    uint32_t aOff[4], bOff[2];   // gmem byte offsets (+128B per chunk)
#pragma unroll
    for (int it = 0; it < 4; ++it) {
        int idx = tid + it * 256;
        int r = idx >> 3, k16 = idx & 7;
        aRel[it] = r * 128 + (((k16 ^ (r & 7)) << 4));
        aOff[it] = (uint32_t)((m0 + r) * K + k16 * 4) * 4u;
    }
#pragma unroll
    for (int it = 0; it < 2; ++it) {
        int idx = tid + it * 256;
        int r = idx >> 3, k16 = idx & 7;
        bRel[it] = r * 128 + (((k16 ^ (r & 7)) << 4));
        bOff[it] = (uint32_t)((n0 + r) * K + k16 * 4) * 4u;
    }

    auto stageF = [&](int s) {
        uint32_t aBase = sbase + s * STAGE_B;
        uint32_t bBase = aBase + A_TILE;
#pragma unroll
        for (int it = 0; it < 4; ++it) {
            cpasync16(aBase + aRel[it], Ab + aOff[it]);
            aOff[it] += BKC * 4;
        }
#pragma unroll
        for (int it = 0; it < 2; ++it) {
            cpasync16(bBase + bRel[it], Bb_ + bOff[it]);
            bOff[it] += BKC * 4;
        }
    };

    stageF(0); CP_COMMIT();
    stageF(1); CP_COMMIT();

    // ---- fragment address precompute ----
    const int r8  = lane & 7;
    const int sel = lane >> 3;                 // 0..3
    const int rowAdd = r8 + ((sel & 2) << 2);  // +8 rows for mats 2,3
    const int colAdd = sel & 1;                // +1 16B col for mats 1,3
    uint32_t colPart[4];
#pragma unroll
    for (int ks = 0; ks < 4; ++ks)
        colPart[ks] = (uint32_t)(((2 * ks + colAdd) ^ r8) << 4);

    uint32_t aRow[2], bRow[2];
#pragma unroll
    for (int g = 0; g < 2; ++g) {
        aRow[g] = (uint32_t)(warpM * 32 + g * 16 + rowAdd) * 128;
        bRow[g] = (uint32_t)(warpN * 32 + g * 16 + rowAdd) * 128 + A_TILE;
    }

    float acc[2][4][4];
#pragma unroll
    for (int mt = 0; mt < 2; ++mt)
#pragma unroll
        for (int nt = 0; nt < 4; ++nt)
#pragma unroll
            for (int r = 0; r < 4; ++r) acc[mt][nt][r] = 0.0f;

    uint32_t aF[2][4], bF[4][2];

    for (int c = 0; c < NC; ++c) {
        CP_WAIT1();
        __syncthreads();
        int cn = c + 2;
        if (cn < NC) {
            int s = cn - (cn >= STAGES ? STAGES : 0);
            while (s >= STAGES) s -= STAGES;
            stageF(cn % 3);
        }
        CP_COMMIT();

        const uint32_t sB = sbase + (c % 3) * STAGE_B;

#pragma unroll
        for (int ks = 0; ks < 4; ++ks) {
            uint32_t cp = colPart[ks];
#pragma unroll
            for (int mt = 0; mt < 2; ++mt) {
                uint32_t r0, r1, r2, r3;
                asm volatile("ldmatrix.sync.aligned.m8n8.x4.shared.b16 {%0,%1,%2,%3}, [%4];"
                             : "=r"(r0), "=r"(r1), "=r"(r2), "=r"(r3)
                             : "r"(sB + aRow[mt] + cp));
                aF[mt][0] = r0; aF[mt][1] = r2;
                aF[mt][2] = r1; aF[mt][3] = r3;
            }
#pragma unroll
            for (int g = 0; g < 2; ++g) {
                uint32_t r0, r1, r2, r3;
                asm volatile("ldmatrix.sync.aligned.m8n8.x4.shared.b16 {%0,%1,%2,%3}, [%4];"
                             : "=r"(r0), "=r"(r1), "=r"(r2), "=r"(r3)
                             : "r"(sB + bRow[g] + cp));
                bF[g * 2][0]     = r0; bF[g * 2][1]     = r1;
                bF[g * 2 + 1][0] = r2; bF[g * 2 + 1][1] = r3;
            }
#pragma unroll
            for (int mt = 0; mt < 2; ++mt)
#pragma unroll
                for (int nt = 0; nt < 4; ++nt)
                    mma_tf32(acc[mt][nt], aF[mt], bF[nt]);
        }
    }

    // ---- epilogue: bias + STG.64 ----
    const int col0 = n0 + warpN * 32 + 2 * (lane & 3);
    float2 bv[4];
#pragma unroll
    for (int nt = 0; nt < 4; ++nt)
        bv[nt] = *(const float2*)(bias + col0 + nt * 8);

    const int row0 = m0 + warpM * 32 + (lane >> 2);
#pragma unroll
    for (int mt = 0; mt < 2; ++mt) {
        int r = row0 + mt * 16;
#pragma unroll
        for (int nt = 0; nt < 4; ++nt) {
            int cc = col0 + nt * 8;
            float2 v0, v1;
            v0.x = acc[mt][nt][0] + bv[nt].x;
            v0.y = acc[mt][nt][1] + bv[nt].y;
            v1.x = acc[mt][nt][2] + bv[nt].x;
            v1.y = acc[mt][nt][3] + bv[nt].y;
            *(float2*)(C + (size_t)r * N + cc)       = v0;
            *(float2*)(C + (size_t)(r + 8) * N + cc) = v1;
        }
    }
}

// ---------------------------------------------------------------------------
// Block attention: one warp per (b, h, block). BS=4, d=64.
// Output rounded to tf32 bits (feeds proj GEMM).
// ---------------------------------------------------------------------------
__global__ __launch_bounds__(256)
void block_attn_kernel(const float* __restrict__ qkv, float* __restrict__ o)
{
    const int gwarp = (blockIdx.x * blockDim.x + threadIdx.x) >> 5;
    const int lane  = threadIdx.x & 31;

    const int nb = gwarp & 1023;
    const int bh = gwarp >> 10;
    const int h  = bh & 15;
    const int b  = bh >> 4;
    const int l0 = nb * BLK;

    const size_t rowBase = ((size_t)(b * Ll + l0)) * NQKV + h * 192;

    float2 q[4], k[4], v[4];
#pragma unroll
    for (int i = 0; i < 4; ++i) {
        const float* p = qkv + rowBase + (size_t)i * NQKV + 2 * lane;
        q[i] = *(const float2*)(p);
        k[i] = *(const float2*)(p + 64);
        v[i] = *(const float2*)(p + 128);
    }

    float s[4][4];
#pragma unroll
    for (int i = 0; i < 4; ++i)
#pragma unroll
        for (int j = 0; j < 4; ++j)
            s[i][j] = fmaf(q[i].y, k[j].y, q[i].x * k[j].x);

#pragma unroll
    for (int i = 0; i < 4; ++i)
#pragma unroll
        for (int j = 0; j < 4; ++j)
#pragma unroll
            for (int off = 16; off > 0; off >>= 1)
                s[i][j] += __shfl_xor_sync(0xffffffffu, s[i][j], off);

    const float scale = 0.125f;
    float2 outv[4];
#pragma unroll
    for (int i = 0; i < 4; ++i) {
        float t0 = s[i][0] * scale, t1 = s[i][1] * scale;
        float t2 = s[i][2] * scale, t3 = s[i][3] * scale;
        float m = fmaxf(fmaxf(t0, t1), fmaxf(t2, t3));
        float e0 = __expf(t0 - m), e1 = __expf(t1 - m);
        float e2 = __expf(t2 - m), e3 = __expf(t3 - m);
        float inv = 1.0f / (e0 + e1 + e2 + e3);
        float p0 = e0 * inv, p1 = e1 * inv, p2 = e2 * inv, p3 = e3 * inv;
        float ox = p0 * v[0].x; ox = fmaf(p1, v[1].x, ox);
        ox = fmaf(p2, v[2].x, ox); ox = fmaf(p3, v[3].x, ox);
        float oy = p0 * v[0].y; oy = fmaf(p1, v[1].y, oy);
        oy = fmaf(p2, v[2].y, oy); oy = fmaf(p3, v[3].y, oy);
        outv[i].x = tf32r(ox); outv[i].y = tf32r(oy);
    }

    const size_t obase = ((size_t)(b * Ll + l0)) * Dd + h * HDIM + 2 * lane;
#pragma unroll
    for (int i = 0; i < 4; ++i)
        *(float2*)(o + obase + (size_t)i * Dd) = outv[i];
}

// ---------------------------------------------------------------------------
extern "C" void kernel_launch(void* const* d_in, const int* in_sizes, int n_in,
                              void* d_out, int out_size)
{
    const float* x     = (const float*)d_in[0];
    const float* Wqkv  = (const float*)d_in[1];
    const float* bqkv  = (const float*)d_in[2];
    const float* Wproj = (const float*)d_in[3];
    const float* bproj = (const float*)d_in[4];
    float* out = (float*)d_out;

    float *qkv, *ob, *xt, *wqt, *wpt;
    cudaGetSymbolAddress((void**)&qkv, g_qkv);
    cudaGetSymbolAddress((void**)&ob,  g_o);
    cudaGetSymbolAddress((void**)&xt,  g_xt);
    cudaGetSymbolAddress((void**)&wqt, g_wqt);
    cudaGetSymbolAddress((void**)&wpt, g_wpt);

    cudaFuncSetAttribute(gemm_mma_kernel,
                         cudaFuncAttributeMaxDynamicSharedMemorySize, GEMM_SMEM);

    // 0) pre-round x; transpose+round weights (Wt[N][K])
    tf32_round_kernel<<<8192, 256>>>((const float4*)x, (float4*)xt, MTOT * Dd / 4);
    {
        dim3 g1(NQKV / 32, Dd / 32);
        transpose_tf32_kernel<<<g1, 256>>>(Wqkv, wqt, Dd, NQKV);
        dim3 g2(Dd / 32, Dd / 32);
        transpose_tf32_kernel<<<g2, 256>>>(Wproj, wpt, Dd, Dd);
    }

    // 1) qkv = x @ W_qkv + b_qkv   (32768 x 3072 x 1024)
    {
        dim3 grid(NQKV / 64, MTOT / 128);
        gemm_mma_kernel<<<grid, 256, GEMM_SMEM>>>(xt, wqt, bqkv, qkv, NQKV, Dd);
    }

    // 2) block attention (tf32-rounded output)
    {
        int nwarps = Bb * Hh * (Ll / BLK);
        block_attn_kernel<<<nwarps / 8, 256>>>(qkv, ob);
    }

    // 3) out = o @ W_proj + b_proj  (32768 x 1024 x 1024)
    {
        dim3 grid(Dd / 64, MTOT / 128);
        gemm_mma_kernel<<<grid, 256, GEMM_SMEM>>>(ob, wpt, bproj, out, Dd, Dd);
    }
}